// round 5
// baseline (speedup 1.0000x reference)
#include <cuda_runtime.h>
#include <cuda_bf16.h>

#define TOKENS 32768
#define DDIM 1024
#define RDIM 48
#define MTILE 256
#define THREADS 512
#define NCTAS (TOKENS / MTILE)   // 128 -> single wave on 148 SMs
#define KC 64
#define NCHUNK (DDIM / KC)       // 16
#define XS_STRIDE 72             // bf16; 144B rows -> conflict-free frag LDS
#define GW_STRIDE 1032           // bf16; 2064B rows
#define YS_STRIDE 52             // bf16
#define WU_STRIDE 56             // bf16; 112B rows
#define H2_STRIDE 56

// ---- shared memory layout (bytes). Regions overlaid by phase. ----
#define OFF_R0    0                               // gw_s (A) / wu_s (C)
#define SZ_R0     (DDIM * WU_STRIDE * 2)          // 114688 (>= gw 99072)
#define OFF_XS    (OFF_R0 + SZ_R0)                // x_s double buffer / h2_s
#define SZ_XS     (2 * MTILE * XS_STRIDE * 2)     // 73728 (>= h2 28672)
#define OFF_YS    (OFF_XS + SZ_XS)                // y bf16: 26624
#define OFF_SUM   (OFF_YS + MTILE * YS_STRIDE * 2)
#define OFF_SUMSQ (OFF_SUM + MTILE * 4)
#define OFF_SGW   (OFF_SUMSQ + MTILE * 4)
#define OFF_CB    (OFF_SGW + RDIM * 4)
#define OFF_C48   (OFF_CB + RDIM * 4)
#define OFF_A48   (OFF_C48 + RDIM * 4)
#define SMEM_TOTAL (OFF_A48 + RDIM * RDIM * 4)    // 226880 B <= 232448

__device__ __forceinline__ float gelu_exact(float v) {
    return 0.5f * v * (1.0f + erff(v * 0.70710678118654752440f));
}

__device__ __forceinline__ void mma_bf16(float* c, unsigned a0, unsigned a1, unsigned a2,
                                         unsigned a3, unsigned b0, unsigned b1) {
    asm volatile(
        "mma.sync.aligned.m16n8k16.row.col.f32.bf16.bf16.f32 "
        "{%0,%1,%2,%3}, {%4,%5,%6,%7}, {%8,%9}, {%0,%1,%2,%3};\n"
        : "+f"(c[0]), "+f"(c[1]), "+f"(c[2]), "+f"(c[3])
        : "r"(a0), "r"(a1), "r"(a2), "r"(a3), "r"(b0), "r"(b1));
}

__device__ __forceinline__ uint2 pack_bf16x4(float a, float b, float c, float d) {
    __nv_bfloat162 p0 = __floats2bfloat162_rn(a, b);
    __nv_bfloat162 p1 = __floats2bfloat162_rn(c, d);
    uint2 pk;
    pk.x = *(unsigned*)&p0;
    pk.y = *(unsigned*)&p1;
    return pk;
}

// ============================================================================
// Fully fused, 512 threads / 256-token tile, 128 CTAs = one wave.
// Weight prep hoisted to start (overlaps first x loads); phase C software-
// pipelined in half-nb groups.
// ============================================================================
__global__ void __launch_bounds__(THREADS, 1) fused_kernel(
    const float* __restrict__ x, const float* __restrict__ gamma,
    const float* __restrict__ beta, const float* __restrict__ w_down,
    const float* __restrict__ w_to_mv, const float* __restrict__ w_equi,
    const float* __restrict__ b_equi, const float* __restrict__ w_from_mv,
    const float* __restrict__ w_up, const float* __restrict__ scale_p,
    float* __restrict__ out)
{
    extern __shared__ char smem[];
    __nv_bfloat16* gw_s = (__nv_bfloat16*)(smem + OFF_R0);
    __nv_bfloat16* wu_s = (__nv_bfloat16*)(smem + OFF_R0);
    __nv_bfloat16* x_s  = (__nv_bfloat16*)(smem + OFF_XS);
    __nv_bfloat16* h2_s = (__nv_bfloat16*)(smem + OFF_XS);
    __nv_bfloat16* y_s  = (__nv_bfloat16*)(smem + OFF_YS);
    float* sum_s   = (float*)(smem + OFF_SUM);
    float* sumsq_s = (float*)(smem + OFF_SUMSQ);
    float* sumgw_s = (float*)(smem + OFF_SGW);
    float* cb_s    = (float*)(smem + OFF_CB);
    float* c48_s   = (float*)(smem + OFF_C48);
    float* A48T_s  = (float*)(smem + OFF_A48);

    const int tid = threadIdx.x, lane = tid & 31, warp = tid >> 5;
    const int g = lane >> 2, t4 = lane & 3;
    const int half = lane >> 4, c16 = lane & 15;       // phase-A load mapping
    const int tok0 = blockIdx.x * MTILE;
    const int mrow = warp * 16;

    float ps[8], pss[8];
    #pragma unroll
    for (int i = 0; i < 8; i++) { ps[i] = 0.f; pss[i] = 0.f; }

    // ---- issue chunk-0 x loads immediately (stats+pack at load time) ----
    uint2 stp[8];
    {
        const float* p = x + (size_t)tok0 * DDIM + c16 * 4;
        #pragma unroll
        for (int i = 0; i < 8; i++) {
            float4 v = *(const float4*)(p + (size_t)(mrow + i * 2 + half) * DDIM);
            ps[i]  += (v.x + v.y) + (v.z + v.w);
            pss[i] += (v.x * v.x + v.y * v.y) + (v.z * v.z + v.w * v.w);
            stp[i] = pack_bf16x4(v.x, v.y, v.z, v.w);
        }
    }

    // ---- stage gw = gamma (*) w_down as bf16 (overlaps x ch0 DRAM latency) ----
    {
        const float4* wd4 = (const float4*)w_down;
        const float4* g4  = (const float4*)gamma;
        for (int i = tid; i < RDIM * DDIM / 4; i += THREADS) {
            int r = i >> 8, c = i & 255;
            float4 w = wd4[i];
            float4 gv = g4[c];
            *(uint2*)(gw_s + r * GW_STRIDE + c * 4) =
                pack_bf16x4(w.x * gv.x, w.y * gv.y, w.z * gv.z, w.w * gv.w);
        }
    }
    __syncthreads();   // gw_s visible to everyone (prep + mma)

    // ---- weight prep, hoisted: sumgw (from bf16 gw), cb, c48, A48T ----
    #pragma unroll 1
    for (int rr = 0; rr < 3; rr++) {
        int r = warp + rr * 16;
        float sg = 0.f, scb = 0.f;
        #pragma unroll
        for (int it = 0; it < 8; it++) {
            int d = it * 128 + lane * 4;
            uint2 pk = *(const uint2*)(gw_s + r * GW_STRIDE + d);
            __nv_bfloat162 b0 = *(__nv_bfloat162*)&pk.x;
            __nv_bfloat162 b1 = *(__nv_bfloat162*)&pk.y;
            sg += __bfloat162float(b0.x) + __bfloat162float(b0.y)
                + __bfloat162float(b1.x) + __bfloat162float(b1.y);
            float4 wv = *(const float4*)(w_down + (size_t)r * DDIM + d);
            float4 bv = *(const float4*)(beta + d);
            scb += wv.x * bv.x + wv.y * bv.y + wv.z * bv.z + wv.w * bv.w;
        }
        #pragma unroll
        for (int off = 16; off; off >>= 1) {
            sg  += __shfl_xor_sync(0xffffffffu, sg, off);
            scb += __shfl_xor_sync(0xffffffffu, scb, off);
        }
        if (lane == 0) { sumgw_s[r] = sg; cb_s[r] = scb; }
    }
    for (int i = tid; i < RDIM; i += THREADS)
        c48_s[i] = __ldg(w_from_mv + i * 16) * __ldg(b_equi);
    for (int i = tid; i < RDIM * RDIM; i += THREADS) {
        int rp = i / RDIM, r = i - rp * RDIM;
        float a = 0.f;
        #pragma unroll
        for (int m = 0; m < 16; m++) {
            int gidx = (m == 0) ? 0 : (m < 5) ? 1 : (m < 11) ? 2 : (m < 15) ? 3 : 4;
            a += __ldg(w_from_mv + r * 16 + m) * __ldg(w_equi + gidx)
               * __ldg(w_to_mv + m * RDIM + rp);
        }
        A48T_s[i] = a;   // A48T[rp][r]
    }

    // ---- phase A mainloop: double-buffered x, stats at load time ----
    float acc[6][4];
    #pragma unroll
    for (int j = 0; j < 6; j++)
        #pragma unroll
        for (int q = 0; q < 4; q++) acc[j][q] = 0.f;

    #pragma unroll 2
    for (int kc = 0; kc < NCHUNK; kc++) {
        __nv_bfloat16* xb = x_s + (kc & 1) * (MTILE * XS_STRIDE);
        #pragma unroll
        for (int i = 0; i < 8; i++)
            *(uint2*)(xb + (mrow + i * 2 + half) * XS_STRIDE + c16 * 4) = stp[i];
        __syncthreads();
        if (kc < NCHUNK - 1) {
            const float* p = x + (size_t)tok0 * DDIM + (kc + 1) * KC + c16 * 4;
            #pragma unroll
            for (int i = 0; i < 8; i++) {
                float4 v = *(const float4*)(p + (size_t)(mrow + i * 2 + half) * DDIM);
                ps[i]  += (v.x + v.y) + (v.z + v.w);
                pss[i] += (v.x * v.x + v.y * v.y) + (v.z * v.z + v.w * v.w);
                stp[i] = pack_bf16x4(v.x, v.y, v.z, v.w);
            }
        }
        #pragma unroll
        for (int kk = 0; kk < KC / 16; kk++) {
            unsigned a0 = *(const unsigned*)(xb + (mrow + g) * XS_STRIDE + kk * 16 + t4 * 2);
            unsigned a1 = *(const unsigned*)(xb + (mrow + g + 8) * XS_STRIDE + kk * 16 + t4 * 2);
            unsigned a2 = *(const unsigned*)(xb + (mrow + g) * XS_STRIDE + kk * 16 + 8 + t4 * 2);
            unsigned a3 = *(const unsigned*)(xb + (mrow + g + 8) * XS_STRIDE + kk * 16 + 8 + t4 * 2);
            int kglob = kc * KC + kk * 16;
            #pragma unroll
            for (int j = 0; j < 6; j++) {
                unsigned b0 = *(const unsigned*)(gw_s + (j * 8 + g) * GW_STRIDE + kglob + t4 * 2);
                unsigned b1 = *(const unsigned*)(gw_s + (j * 8 + g) * GW_STRIDE + kglob + 8 + t4 * 2);
                mma_bf16(acc[j], a0, a1, a2, a3, b0, b1);
            }
        }
    }

    // ---- stats: one reduction over the 16 lanes sharing each row ----
    #pragma unroll
    for (int i = 0; i < 8; i++) {
        float s = ps[i], q = pss[i];
        #pragma unroll
        for (int off = 8; off; off >>= 1) {
            s += __shfl_xor_sync(0xffffffffu, s, off);
            q += __shfl_xor_sync(0xffffffffu, q, off);
        }
        if (c16 == 0) {
            sum_s[mrow + i * 2 + half] = s;
            sumsq_s[mrow + i * 2 + half] = q;
        }
    }
    __syncthreads();
    if (tid < MTILE) {
        float mu  = sum_s[tid] * (1.0f / DDIM);
        float var = sumsq_s[tid] * (1.0f / DDIM) - mu * mu;
        sum_s[tid]   = mu;
        sumsq_s[tid] = rsqrtf(var + 1e-5f);
    }
    __syncthreads();

    // ---- epilogue: y = gelu(rinv*(acc - mu*sumgw) + cb) -> bf16 ----
    {
        int r0 = mrow + g, r1 = r0 + 8;
        float mu0 = sum_s[r0], ri0 = sumsq_s[r0];
        float mu1 = sum_s[r1], ri1 = sumsq_s[r1];
        #pragma unroll
        for (int j = 0; j < 6; j++) {
            int c0 = j * 8 + t4 * 2, c1 = c0 + 1;
            float y00 = gelu_exact(ri0 * (acc[j][0] - mu0 * sumgw_s[c0]) + cb_s[c0]);
            float y01 = gelu_exact(ri0 * (acc[j][1] - mu0 * sumgw_s[c1]) + cb_s[c1]);
            float y10 = gelu_exact(ri1 * (acc[j][2] - mu1 * sumgw_s[c0]) + cb_s[c0]);
            float y11 = gelu_exact(ri1 * (acc[j][3] - mu1 * sumgw_s[c1]) + cb_s[c1]);
            *(__nv_bfloat162*)(y_s + r0 * YS_STRIDE + c0) = __floats2bfloat162_rn(y00, y01);
            *(__nv_bfloat162*)(y_s + r1 * YS_STRIDE + c0) = __floats2bfloat162_rn(y10, y11);
        }
    }

    // ---- stage w_up as bf16 into region0 (gw_s dead after mainloop) ----
    {
        const float4* wu4 = (const float4*)w_up;
        for (int i = tid; i < DDIM * RDIM / 4; i += THREADS) {
            int d = i / 12, q = i - d * 12;
            float4 v = wu4[i];
            *(uint2*)(wu_s + d * WU_STRIDE + q * 4) = pack_bf16x4(v.x, v.y, v.z, v.w);
        }
    }
    __syncthreads();

    // ---- middle: h2 = gelu(A48 @ y + c48) -> bf16 (overlays x_s; x_s dead) ----
    {
        int t = tid >> 1;
        int rbase = (tid & 1) * 24;
        const __nv_bfloat16* yrow = y_s + t * YS_STRIDE;
        float h2v[24];
        #pragma unroll
        for (int r = 0; r < 24; r++) h2v[r] = c48_s[rbase + r];
        #pragma unroll 4
        for (int kp2 = 0; kp2 < RDIM / 2; kp2++) {
            __nv_bfloat162 yp = *(const __nv_bfloat162*)(yrow + kp2 * 2);
            float yv0 = __bfloat162float(yp.x), yv1 = __bfloat162float(yp.y);
            const float* a0 = A48T_s + (kp2 * 2) * RDIM + rbase;
            const float* a1 = a0 + RDIM;
            #pragma unroll
            for (int r = 0; r < 24; r++) h2v[r] += yv0 * a0[r] + yv1 * a1[r];
        }
        __nv_bfloat16* op = h2_s + t * H2_STRIDE + rbase;
        #pragma unroll
        for (int r = 0; r < 24; r += 2) {
            __nv_bfloat162 p = __floats2bfloat162_rn(gelu_exact(h2v[r]), gelu_exact(h2v[r + 1]));
            *(__nv_bfloat162*)(op + r) = p;
        }
    }
    __syncthreads();

    // ---- phase C: out = x + scale * (h2 @ w_up^T), software-pipelined ----
    float scale = __ldg(scale_p);
    unsigned afr[3][4];
    #pragma unroll
    for (int kk = 0; kk < 3; kk++) {
        afr[kk][0] = *(const unsigned*)(h2_s + (mrow + g) * H2_STRIDE + kk * 16 + t4 * 2);
        afr[kk][1] = *(const unsigned*)(h2_s + (mrow + g + 8) * H2_STRIDE + kk * 16 + t4 * 2);
        afr[kk][2] = *(const unsigned*)(h2_s + (mrow + g) * H2_STRIDE + kk * 16 + 8 + t4 * 2);
        afr[kk][3] = *(const unsigned*)(h2_s + (mrow + g + 8) * H2_STRIDE + kk * 16 + 8 + t4 * 2);
    }

    const size_t row0 = (size_t)(tok0 + mrow + g) * DDIM;
    const size_t row1 = row0 + 8 * (size_t)DDIM;

    // 32 groups: gi -> nb = gi>>1, j-range = (gi&1)*4 .. +4.  Two xv buffers.
    float2 xva[2][8];
    {
        #pragma unroll
        for (int j = 0; j < 4; j++) {
            int c = j * 8 + t4 * 2;
            xva[0][j * 2]     = *(const float2*)(x + row0 + c);
            xva[0][j * 2 + 1] = *(const float2*)(x + row1 + c);
        }
    }
    #pragma unroll 2
    for (int gi = 0; gi < 32; gi++) {
        const int cur = gi & 1, nxt = cur ^ 1;
        if (gi < 31) {
            int gn = gi + 1;
            int cbase = (gn >> 1) * 64 + (gn & 1) * 32;
            #pragma unroll
            for (int j = 0; j < 4; j++) {
                int c = cbase + j * 8 + t4 * 2;
                xva[nxt][j * 2]     = *(const float2*)(x + row0 + c);
                xva[nxt][j * 2 + 1] = *(const float2*)(x + row1 + c);
            }
        }
        int nb = gi >> 1, j0 = (gi & 1) * 4;
        float uacc[4][4];
        #pragma unroll
        for (int j = 0; j < 4; j++)
            #pragma unroll
            for (int q = 0; q < 4; q++) uacc[j][q] = 0.f;
        #pragma unroll
        for (int kk = 0; kk < 3; kk++) {
            #pragma unroll
            for (int j = 0; j < 4; j++) {
                int n = nb * 64 + (j0 + j) * 8 + g;
                unsigned b0 = *(const unsigned*)(wu_s + n * WU_STRIDE + kk * 16 + t4 * 2);
                unsigned b1 = *(const unsigned*)(wu_s + n * WU_STRIDE + kk * 16 + 8 + t4 * 2);
                mma_bf16(uacc[j], afr[kk][0], afr[kk][1], afr[kk][2], afr[kk][3], b0, b1);
            }
        }
        #pragma unroll
        for (int j = 0; j < 4; j++) {
            int c = nb * 64 + (j0 + j) * 8 + t4 * 2;
            float2 x0 = xva[cur][j * 2], x1 = xva[cur][j * 2 + 1];
            float2 o0 = make_float2(x0.x + scale * uacc[j][0], x0.y + scale * uacc[j][1]);
            float2 o1 = make_float2(x1.x + scale * uacc[j][2], x1.y + scale * uacc[j][3]);
            __stcs((float2*)(out + row0 + c), o0);
            __stcs((float2*)(out + row1 + c), o1);
        }
    }
}

extern "C" void kernel_launch(void* const* d_in, const int* in_sizes, int n_in,
                              void* d_out, int out_size) {
    const float* x         = (const float*)d_in[0];
    const float* gamma     = (const float*)d_in[1];
    const float* beta      = (const float*)d_in[2];
    const float* w_down    = (const float*)d_in[3];
    const float* w_to_mv   = (const float*)d_in[4];
    const float* w_equi    = (const float*)d_in[5];
    const float* b_equi    = (const float*)d_in[6];
    const float* w_from_mv = (const float*)d_in[7];
    const float* w_up      = (const float*)d_in[8];
    const float* scale     = (const float*)d_in[9];
    float* out = (float*)d_out;

    cudaFuncSetAttribute(fused_kernel, cudaFuncAttributeMaxDynamicSharedMemorySize, SMEM_TOTAL);
    fused_kernel<<<NCTAS, THREADS, SMEM_TOTAL>>>(x, gamma, beta, w_down, w_to_mv, w_equi,
                                                 b_equi, w_from_mv, w_up, scale, out);
}

// round 8
// speedup vs baseline: 1.2298x; 1.2298x over previous
#include <cuda_runtime.h>
#include <cuda_bf16.h>

#define TOKENS 32768
#define DDIM 1024
#define RDIM 48
#define MTILE 256
#define THREADS 512
#define NCTAS (TOKENS / MTILE)   // 128 CTAs -> one wave
#define KC 32
#define NCHUNK (DDIM / KC)       // 32

// fp32 smem strides (elements)
#define XST_F 36                 // 144B rows -> <=2-way on LDS.64 (floor)
#define WDST_F 36
#define WUST_F 52
#define YS_STRIDE 52             // bf16
#define H2_STRIDE 56             // bf16

#define XSTAGE_B  (MTILE * XST_F * 4)      // 36864
#define WDSTAGE_B (RDIM * WDST_F * 4)      // 6912
#define NSTAGE 3

// ---- smem layout (bytes) ----
#define OFF_XST 0                                  // x fp32 stages (A and C)
#define OFF_WST (OFF_XST + NSTAGE * XSTAGE_B)      // 110592: wd stages (A) / wu stages (C)
#define OFF_H2  (OFF_WST + NSTAGE * WDSTAGE_B)     // 131328: h2 bf16 28672
#define OFF_Y   (OFF_H2 + MTILE * H2_STRIDE * 2)   // 160000: y bf16 26624
#define OFF_GAM (OFF_Y + MTILE * YS_STRIDE * 2)    // 186624: gamma fp32 4096
#define OFF_SUM (OFF_GAM + DDIM * 4)               // 190720
#define OFF_SSQ (OFF_SUM + MTILE * 4)
#define OFF_SGW (OFF_SSQ + MTILE * 4)
#define OFF_CB  (OFF_SGW + RDIM * 4)
#define OFF_C48 (OFF_CB + RDIM * 4)
#define OFF_A48 (OFF_C48 + RDIM * 4)
#define SMEM_TOTAL (OFF_A48 + RDIM * RDIM * 4)     // 202560 <= 232448

__device__ __forceinline__ float gelu_exact(float v) {
    return 0.5f * v * (1.0f + erff(v * 0.70710678118654752440f));
}

__device__ __forceinline__ void mma_bf16(float* c, unsigned a0, unsigned a1, unsigned a2,
                                         unsigned a3, unsigned b0, unsigned b1) {
    asm volatile(
        "mma.sync.aligned.m16n8k16.row.col.f32.bf16.bf16.f32 "
        "{%0,%1,%2,%3}, {%4,%5,%6,%7}, {%8,%9}, {%0,%1,%2,%3};\n"
        : "+f"(c[0]), "+f"(c[1]), "+f"(c[2]), "+f"(c[3])
        : "r"(a0), "r"(a1), "r"(a2), "r"(a3), "r"(b0), "r"(b1));
}

__device__ __forceinline__ unsigned pack2(float a, float b) {
    __nv_bfloat162 p = __floats2bfloat162_rn(a, b);
    return *(unsigned*)&p;
}

__device__ __forceinline__ void cp16(unsigned dst, const void* src) {
    asm volatile("cp.async.cg.shared.global [%0], [%1], 16;\n" :: "r"(dst), "l"(src));
}
__device__ __forceinline__ void cp_commit() {
    asm volatile("cp.async.commit_group;\n");
}
template <int N>
__device__ __forceinline__ void cp_wait() {
    asm volatile("cp.async.wait_group %0;\n" :: "n"(N));
}

// ============================================================================
__global__ void __launch_bounds__(THREADS, 1) fused_kernel(
    const float* __restrict__ x, const float* __restrict__ gamma,
    const float* __restrict__ beta, const float* __restrict__ w_down,
    const float* __restrict__ w_to_mv, const float* __restrict__ w_equi,
    const float* __restrict__ b_equi, const float* __restrict__ w_from_mv,
    const float* __restrict__ w_up, const float* __restrict__ scale_p,
    float* __restrict__ out)
{
    extern __shared__ char smem[];
    const unsigned sbase = (unsigned)__cvta_generic_to_shared(smem);
    float* gamma_s = (float*)(smem + OFF_GAM);
    __nv_bfloat16* h2_s = (__nv_bfloat16*)(smem + OFF_H2);
    __nv_bfloat16* y_s  = (__nv_bfloat16*)(smem + OFF_Y);
    float* sum_s   = (float*)(smem + OFF_SUM);
    float* sumsq_s = (float*)(smem + OFF_SSQ);
    float* sumgw_s = (float*)(smem + OFF_SGW);
    float* cb_s    = (float*)(smem + OFF_CB);
    float* c48_s   = (float*)(smem + OFF_C48);
    float* A48T_s  = (float*)(smem + OFF_A48);

    const int tid = threadIdx.x, lane = tid & 31, warp = tid >> 5;
    const int g = lane >> 2, t4 = lane & 3;
    const int tok0 = blockIdx.x * MTILE;
    const int mrow = warp * 16;

    // thread's cp.async mappings
    const int xrow = tid >> 3, xc4 = (tid & 7) * 4;           // x: 4 ops (rows +64p)
    const int wdrow = tid >> 3, wdc4 = (tid & 7) * 4;         // wd: tid<384
    const int wurow = tid / 12, wuc4 = (tid % 12) * 4;        // wu: tid<384

    // ---------------- phase A: issue chunk 0 ASAP ----------------
    {
        unsigned xd = sbase + OFF_XST + (xrow * XST_F + xc4) * 4;
        const float* xsrc = x + (size_t)(tok0 + xrow) * DDIM + xc4;
        #pragma unroll
        for (int p = 0; p < 4; p++)
            cp16(xd + p * 64 * XST_F * 4, xsrc + (size_t)p * 64 * DDIM);
        if (tid < 384)
            cp16(sbase + OFF_WST + (wdrow * WDST_F + wdc4) * 4,
                 w_down + (size_t)wdrow * DDIM + wdc4);
        cp_commit();
    }

    // ---------------- prologue prep (overlaps chunk-0 flight) ----------------
    {
        const float4* g4 = (const float4*)gamma;
        for (int i = tid; i < DDIM / 4; i += THREADS)
            *(float4*)(gamma_s + i * 4) = g4[i];
    }
    // sumgw (bf16-rounded w, x-side gamma) and cb
    #pragma unroll 1
    for (int rr = 0; rr < 3; rr++) {
        int r = warp + rr * 16;
        float sg = 0.f, scb = 0.f;
        #pragma unroll
        for (int it = 0; it < 8; it++) {
            int d = it * 128 + lane * 4;
            float4 wv = *(const float4*)(w_down + (size_t)r * DDIM + d);
            float4 gv = *(const float4*)(gamma + d);
            float4 bv = *(const float4*)(beta + d);
            sg += gv.x * __bfloat162float(__float2bfloat16(wv.x))
                + gv.y * __bfloat162float(__float2bfloat16(wv.y))
                + gv.z * __bfloat162float(__float2bfloat16(wv.z))
                + gv.w * __bfloat162float(__float2bfloat16(wv.w));
            scb += wv.x * bv.x + wv.y * bv.y + wv.z * bv.z + wv.w * bv.w;
        }
        #pragma unroll
        for (int off = 16; off; off >>= 1) {
            sg  += __shfl_xor_sync(0xffffffffu, sg, off);
            scb += __shfl_xor_sync(0xffffffffu, scb, off);
        }
        if (lane == 0) { sumgw_s[r] = sg; cb_s[r] = scb; }
    }
    for (int i = tid; i < RDIM; i += THREADS)
        c48_s[i] = __ldg(w_from_mv + i * 16) * __ldg(b_equi);
    for (int i = tid; i < RDIM * RDIM; i += THREADS) {
        int rp = i / RDIM, r = i - rp * RDIM;
        float a = 0.f;
        #pragma unroll
        for (int m = 0; m < 16; m++) {
            int gidx = (m == 0) ? 0 : (m < 5) ? 1 : (m < 11) ? 2 : (m < 15) ? 3 : 4;
            a += __ldg(w_from_mv + r * 16 + m) * __ldg(w_equi + gidx)
               * __ldg(w_to_mv + m * RDIM + rp);
        }
        A48T_s[i] = a;   // A48T[rp][r]
    }

    // ---------------- phase A mainloop ----------------
    float acc[6][4];
    #pragma unroll
    for (int j = 0; j < 6; j++)
        #pragma unroll
        for (int q = 0; q < 4; q++) acc[j][q] = 0.f;
    float ps0 = 0.f, pss0 = 0.f, ps1 = 0.f, pss1 = 0.f;

    #pragma unroll 1
    for (int kc = 0; kc < NCHUNK; kc++) {
        if (kc < NCHUNK - 1) {   // issue chunk kc+1
            int kn = kc + 1, st = kn % NSTAGE;
            unsigned xd = sbase + OFF_XST + st * XSTAGE_B + (xrow * XST_F + xc4) * 4;
            const float* xsrc = x + (size_t)(tok0 + xrow) * DDIM + kn * KC + xc4;
            #pragma unroll
            for (int p = 0; p < 4; p++)
                cp16(xd + p * 64 * XST_F * 4, xsrc + (size_t)p * 64 * DDIM);
            if (tid < 384)
                cp16(sbase + OFF_WST + st * WDSTAGE_B + (wdrow * WDST_F + wdc4) * 4,
                     w_down + (size_t)wdrow * DDIM + kn * KC + wdc4);
            cp_commit();
            cp_wait<1>();
        } else {
            cp_wait<0>();
        }
        __syncthreads();

        const float* xs  = (const float*)(smem + OFF_XST + (kc % NSTAGE) * XSTAGE_B);
        const float* wds = (const float*)(smem + OFF_WST + (kc % NSTAGE) * WDSTAGE_B);
        #pragma unroll
        for (int kk = 0; kk < 2; kk++) {
            int cb = kk * 16;
            int kg = kc * KC + cb;
            float2 p00 = *(const float2*)(xs + (mrow + g) * XST_F + cb + t4 * 2);
            float2 p10 = *(const float2*)(xs + (mrow + g + 8) * XST_F + cb + t4 * 2);
            float2 p01 = *(const float2*)(xs + (mrow + g) * XST_F + cb + 8 + t4 * 2);
            float2 p11 = *(const float2*)(xs + (mrow + g + 8) * XST_F + cb + 8 + t4 * 2);
            float2 ga = *(const float2*)(gamma_s + kg + t4 * 2);
            float2 gb = *(const float2*)(gamma_s + kg + 8 + t4 * 2);
            ps0  += (p00.x + p00.y) + (p01.x + p01.y);
            pss0 += (p00.x * p00.x + p00.y * p00.y) + (p01.x * p01.x + p01.y * p01.y);
            ps1  += (p10.x + p10.y) + (p11.x + p11.y);
            pss1 += (p10.x * p10.x + p10.y * p10.y) + (p11.x * p11.x + p11.y * p11.y);
            unsigned a0 = pack2(p00.x * ga.x, p00.y * ga.y);
            unsigned a1 = pack2(p10.x * ga.x, p10.y * ga.y);
            unsigned a2 = pack2(p01.x * gb.x, p01.y * gb.y);
            unsigned a3 = pack2(p11.x * gb.x, p11.y * gb.y);
            #pragma unroll
            for (int j = 0; j < 6; j++) {
                float2 q0 = *(const float2*)(wds + (j * 8 + g) * WDST_F + cb + t4 * 2);
                float2 q1 = *(const float2*)(wds + (j * 8 + g) * WDST_F + cb + 8 + t4 * 2);
                mma_bf16(acc[j], a0, a1, a2, a3, pack2(q0.x, q0.y), pack2(q1.x, q1.y));
            }
        }
    }

    // ---- stats reduce over the 4 t4-lanes sharing each row ----
    {
        #pragma unroll
        for (int off = 1; off <= 2; off <<= 1) {
            ps0  += __shfl_xor_sync(0xffffffffu, ps0, off);
            pss0 += __shfl_xor_sync(0xffffffffu, pss0, off);
            ps1  += __shfl_xor_sync(0xffffffffu, ps1, off);
            pss1 += __shfl_xor_sync(0xffffffffu, pss1, off);
        }
        if (t4 == 0) {
            sum_s[mrow + g] = ps0;     sumsq_s[mrow + g] = pss0;
            sum_s[mrow + g + 8] = ps1; sumsq_s[mrow + g + 8] = pss1;
        }
    }
    __syncthreads();
    if (tid < MTILE) {
        float mu  = sum_s[tid] * (1.0f / DDIM);
        float var = sumsq_s[tid] * (1.0f / DDIM) - mu * mu;
        sum_s[tid]   = mu;
        sumsq_s[tid] = rsqrtf(var + 1e-5f);
    }
    __syncthreads();

    // ---- y = gelu(rinv*(acc - mu*sumgw) + cb) -> bf16 ----
    {
        int r0 = mrow + g, r1 = r0 + 8;
        float mu0 = sum_s[r0], ri0 = sumsq_s[r0];
        float mu1 = sum_s[r1], ri1 = sumsq_s[r1];
        #pragma unroll
        for (int j = 0; j < 6; j++) {
            int c0 = j * 8 + t4 * 2, c1 = c0 + 1;
            float y00 = gelu_exact(ri0 * (acc[j][0] - mu0 * sumgw_s[c0]) + cb_s[c0]);
            float y01 = gelu_exact(ri0 * (acc[j][1] - mu0 * sumgw_s[c1]) + cb_s[c1]);
            float y10 = gelu_exact(ri1 * (acc[j][2] - mu1 * sumgw_s[c0]) + cb_s[c0]);
            float y11 = gelu_exact(ri1 * (acc[j][3] - mu1 * sumgw_s[c1]) + cb_s[c1]);
            *(__nv_bfloat162*)(y_s + r0 * YS_STRIDE + c0) = __floats2bfloat162_rn(y00, y01);
            *(__nv_bfloat162*)(y_s + r1 * YS_STRIDE + c0) = __floats2bfloat162_rn(y10, y11);
        }
    }
    __syncthreads();

    // ---- middle: h2 = gelu(A48 @ y + c48) -> bf16 ----
    {
        int t = tid >> 1;
        int rbase = (tid & 1) * 24;
        const __nv_bfloat16* yrow = y_s + t * YS_STRIDE;
        float h2v[24];
        #pragma unroll
        for (int r = 0; r < 24; r++) h2v[r] = c48_s[rbase + r];
        #pragma unroll 4
        for (int kp2 = 0; kp2 < RDIM / 2; kp2++) {
            __nv_bfloat162 yp = *(const __nv_bfloat162*)(yrow + kp2 * 2);
            float yv0 = __bfloat162float(yp.x), yv1 = __bfloat162float(yp.y);
            const float* a0 = A48T_s + (kp2 * 2) * RDIM + rbase;
            const float* a1 = a0 + RDIM;
            #pragma unroll
            for (int r = 0; r < 24; r++) h2v[r] += yv0 * a0[r] + yv1 * a1[r];
        }
        __nv_bfloat16* op = h2_s + t * H2_STRIDE + rbase;
        #pragma unroll
        for (int r = 0; r < 24; r += 2) {
            __nv_bfloat162 p = __floats2bfloat162_rn(gelu_exact(h2v[r]), gelu_exact(h2v[r + 1]));
            *(__nv_bfloat162*)(op + r) = p;
        }
    }
    __syncthreads();

    // ---------------- phase C: out = x + scale*(h2 @ w_up^T) ----------------
    float scale = __ldg(scale_p);
    unsigned afr[3][4];
    #pragma unroll
    for (int kk = 0; kk < 3; kk++) {
        afr[kk][0] = *(const unsigned*)(h2_s + (mrow + g) * H2_STRIDE + kk * 16 + t4 * 2);
        afr[kk][1] = *(const unsigned*)(h2_s + (mrow + g + 8) * H2_STRIDE + kk * 16 + t4 * 2);
        afr[kk][2] = *(const unsigned*)(h2_s + (mrow + g) * H2_STRIDE + kk * 16 + 8 + t4 * 2);
        afr[kk][3] = *(const unsigned*)(h2_s + (mrow + g + 8) * H2_STRIDE + kk * 16 + 8 + t4 * 2);
    }

    // issue chunk 0 (x cols 0..31 + wu rows 0..31)
    {
        unsigned xd = sbase + OFF_XST + (xrow * XST_F + xc4) * 4;
        const float* xsrc = x + (size_t)(tok0 + xrow) * DDIM + xc4;
        #pragma unroll
        for (int p = 0; p < 4; p++)
            cp16(xd + p * 64 * XST_F * 4, xsrc + (size_t)p * 64 * DDIM);
        if (tid < 384)
            cp16(sbase + OFF_WST + (wurow * WUST_F + wuc4) * 4,
                 w_up + (size_t)wurow * RDIM + wuc4);
        cp_commit();
    }

    #pragma unroll 1
    for (int nc = 0; nc < NCHUNK; nc++) {
        if (nc < NCHUNK - 1) {
            int nn = nc + 1, st = nn % NSTAGE;
            unsigned xd = sbase + OFF_XST + st * XSTAGE_B + (xrow * XST_F + xc4) * 4;
            const float* xsrc = x + (size_t)(tok0 + xrow) * DDIM + nn * KC + xc4;
            #pragma unroll
            for (int p = 0; p < 4; p++)
                cp16(xd + p * 64 * XST_F * 4, xsrc + (size_t)p * 64 * DDIM);
            if (tid < 384)
                cp16(sbase + OFF_WST + st * WDSTAGE_B + (wurow * WUST_F + wuc4) * 4,
                     w_up + (size_t)(nn * KC + wurow) * RDIM + wuc4);
            cp_commit();
            cp_wait<1>();
        } else {
            cp_wait<0>();
        }
        __syncthreads();

        const float* xs  = (const float*)(smem + OFF_XST + (nc % NSTAGE) * XSTAGE_B);
        const float* wus = (const float*)(smem + OFF_WST + (nc % NSTAGE) * WDSTAGE_B);

        float uacc[4][4];
        #pragma unroll
        for (int j = 0; j < 4; j++)
            #pragma unroll
            for (int q = 0; q < 4; q++) uacc[j][q] = 0.f;

        #pragma unroll
        for (int kk = 0; kk < 3; kk++) {
            #pragma unroll
            for (int j = 0; j < 4; j++) {
                float2 q0 = *(const float2*)(wus + (j * 8 + g) * WUST_F + kk * 16 + t4 * 2);
                float2 q1 = *(const float2*)(wus + (j * 8 + g) * WUST_F + kk * 16 + 8 + t4 * 2);
                mma_bf16(uacc[j], afr[kk][0], afr[kk][1], afr[kk][2], afr[kk][3],
                         pack2(q0.x, q0.y), pack2(q1.x, q1.y));
            }
        }
        size_t row0 = (size_t)(tok0 + mrow + g) * DDIM + nc * KC;
        size_t row1 = row0 + 8 * (size_t)DDIM;
        #pragma unroll
        for (int j = 0; j < 4; j++) {
            int lc = j * 8 + t4 * 2;
            float2 xv0 = *(const float2*)(xs + (mrow + g) * XST_F + lc);
            float2 xv1 = *(const float2*)(xs + (mrow + g + 8) * XST_F + lc);
            float2 o0 = make_float2(xv0.x + scale * uacc[j][0], xv0.y + scale * uacc[j][1]);
            float2 o1 = make_float2(xv1.x + scale * uacc[j][2], xv1.y + scale * uacc[j][3]);
            __stcs((float2*)(out + row0 + lc), o0);
            __stcs((float2*)(out + row1 + lc), o1);
        }
    }
}

extern "C" void kernel_launch(void* const* d_in, const int* in_sizes, int n_in,
                              void* d_out, int out_size) {
    const float* x         = (const float*)d_in[0];
    const float* gamma     = (const float*)d_in[1];
    const float* beta      = (const float*)d_in[2];
    const float* w_down    = (const float*)d_in[3];
    const float* w_to_mv   = (const float*)d_in[4];
    const float* w_equi    = (const float*)d_in[5];
    const float* b_equi    = (const float*)d_in[6];
    const float* w_from_mv = (const float*)d_in[7];
    const float* w_up      = (const float*)d_in[8];
    const float* scale     = (const float*)d_in[9];
    float* out = (float*)d_out;

    cudaFuncSetAttribute(fused_kernel, cudaFuncAttributeMaxDynamicSharedMemorySize, SMEM_TOTAL);
    fused_kernel<<<NCTAS, THREADS, SMEM_TOTAL>>>(x, gamma, beta, w_down, w_to_mv, w_equi,
                                                 b_equi, w_from_mv, w_up, scale, out);
}

// round 9
// speedup vs baseline: 1.6581x; 1.3482x over previous
#include <cuda_runtime.h>
#include <cuda_bf16.h>

#define TOKENS 32768
#define DDIM 1024
#define RDIM 48
#define MTILE 256
#define THREADS 512
#define NCTAS (TOKENS / MTILE)   // 128 CTAs -> one wave
#define KC 32
#define NCHUNK (DDIM / KC)       // 32
#define NSTAGE 4

#define XST_F 36                 // fp32 elems; 144B rows
#define WDST 40                  // bf16 elems; 80B rows (16B aligned, conflict-free)
#define WUST 56                  // bf16 elems; 112B rows (16B aligned, conflict-free)
#define YS_STRIDE 52             // bf16
#define H2_STRIDE 56             // bf16

#define XSTAGE_B (MTILE * XST_F * 4)     // 36864
#define WSTAGE_B (RDIM * WDST * 2)       // 3840 (>= wu stage 3584)

// ---- smem layout (bytes) ----
#define OFF_XST 0                                   // 4 x-stages: 147456
#define OFF_WST (OFF_XST + NSTAGE * XSTAGE_B)       // 4 w-stages: 15360
#define OFF_H2  (OFF_WST + NSTAGE * WSTAGE_B)       // 28672
#define OFF_Y   (OFF_H2 + MTILE * H2_STRIDE * 2)    // 26624
#define OFF_SUM (OFF_Y + MTILE * YS_STRIDE * 2)
#define OFF_SSQ (OFF_SUM + MTILE * 4)
#define OFF_SGW (OFF_SSQ + MTILE * 4)
#define OFF_CB  (OFF_SGW + RDIM * 4)
#define OFF_C48 (OFF_CB + RDIM * 4)
#define OFF_A48 (OFF_C48 + RDIM * 4)
#define SMEM_TOTAL (OFF_A48 + RDIM * RDIM * 4)      // 229952 <= 232448

// ---- global scratch (prep output) ----
__device__ __align__(16) __nv_bfloat16 g_gw[RDIM * DDIM];   // gamma (*) w_down
__device__ __align__(16) __nv_bfloat16 g_wu[DDIM * RDIM];
__device__ float g_sumgw[RDIM];
__device__ float g_cb[RDIM];
__device__ float g_c48[RDIM];
__device__ float g_A48T[RDIM * RDIM];

__device__ __forceinline__ float gelu_exact(float v) {
    return 0.5f * v * (1.0f + erff(v * 0.70710678118654752440f));
}

__device__ __forceinline__ void mma_bf16(float* c, unsigned a0, unsigned a1, unsigned a2,
                                         unsigned a3, unsigned b0, unsigned b1) {
    asm volatile(
        "mma.sync.aligned.m16n8k16.row.col.f32.bf16.bf16.f32 "
        "{%0,%1,%2,%3}, {%4,%5,%6,%7}, {%8,%9}, {%0,%1,%2,%3};\n"
        : "+f"(c[0]), "+f"(c[1]), "+f"(c[2]), "+f"(c[3])
        : "r"(a0), "r"(a1), "r"(a2), "r"(a3), "r"(b0), "r"(b1));
}

__device__ __forceinline__ unsigned pack2(float a, float b) {
    __nv_bfloat162 p = __floats2bfloat162_rn(a, b);
    return *(unsigned*)&p;
}

__device__ __forceinline__ void cp16(unsigned dst, const void* src) {
    asm volatile("cp.async.cg.shared.global [%0], [%1], 16;\n" :: "r"(dst), "l"(src));
}
__device__ __forceinline__ void cp_commit() {
    asm volatile("cp.async.commit_group;\n");
}
template <int N>
__device__ __forceinline__ void cp_wait() {
    asm volatile("cp.async.wait_group %0;\n" :: "n"(N));
}

// ============================================================================
// prep: gamma-folded w_down -> bf16, w_up -> bf16, sumgw/cb, collapsed 48x48.
// ============================================================================
__global__ void prep_kernel(const float* __restrict__ gamma, const float* __restrict__ beta,
                            const float* __restrict__ w_down, const float* __restrict__ w_to_mv,
                            const float* __restrict__ w_equi, const float* __restrict__ b_equi,
                            const float* __restrict__ w_from_mv, const float* __restrict__ w_up) {
    int tid = threadIdx.x, lane = tid & 31;
    int gtid = blockIdx.x * blockDim.x + tid;
    int nth = gridDim.x * blockDim.x;
    int gwarp = gtid >> 5;

    if (gwarp < RDIM) {
        int r = gwarp;
        float s = 0.f, cb = 0.f;
        for (int d = lane; d < DDIM; d += 32) {
            float w = w_down[r * DDIM + d];
            __nv_bfloat16 b = __float2bfloat16(w * gamma[d]);
            g_gw[r * DDIM + d] = b;
            s += __bfloat162float(b);
            cb += w * beta[d];
        }
        #pragma unroll
        for (int off = 16; off; off >>= 1) {
            s  += __shfl_xor_sync(0xffffffffu, s, off);
            cb += __shfl_xor_sync(0xffffffffu, cb, off);
        }
        if (lane == 0) { g_sumgw[r] = s; g_cb[r] = cb; }
    }
    for (int i = gtid; i < DDIM * RDIM; i += nth)
        g_wu[i] = __float2bfloat16(w_up[i]);
    for (int i = gtid; i < RDIM * RDIM; i += nth) {
        int rp = i / RDIM, r = i - rp * RDIM;
        float a = 0.f;
        #pragma unroll
        for (int m = 0; m < 16; m++) {
            int gidx = (m == 0) ? 0 : (m < 5) ? 1 : (m < 11) ? 2 : (m < 15) ? 3 : 4;
            a += w_from_mv[r * 16 + m] * w_equi[gidx] * w_to_mv[m * RDIM + rp];
        }
        g_A48T[i] = a;
    }
    for (int i = gtid; i < RDIM; i += nth)
        g_c48[i] = w_from_mv[i * 16] * b_equi[0];
}

// ============================================================================
__global__ void __launch_bounds__(THREADS, 1) fused_kernel(
    const float* __restrict__ x, const float* __restrict__ scale_p,
    float* __restrict__ out)
{
    extern __shared__ char smem[];
    const unsigned sbase = (unsigned)__cvta_generic_to_shared(smem);
    __nv_bfloat16* h2_s = (__nv_bfloat16*)(smem + OFF_H2);
    __nv_bfloat16* y_s  = (__nv_bfloat16*)(smem + OFF_Y);
    float* sum_s   = (float*)(smem + OFF_SUM);
    float* sumsq_s = (float*)(smem + OFF_SSQ);
    float* sumgw_s = (float*)(smem + OFF_SGW);
    float* cb_s    = (float*)(smem + OFF_CB);
    float* c48_s   = (float*)(smem + OFF_C48);
    float* A48T_s  = (float*)(smem + OFF_A48);

    const int tid = threadIdx.x, lane = tid & 31, warp = tid >> 5;
    const int g = lane >> 2, t4 = lane & 3;
    const int tok0 = blockIdx.x * MTILE;
    const int mrow = warp * 16;

    const int xrow = tid >> 3, xc4 = (tid & 7) * 4;   // x cp mapping: 4 ops/thread

    // ---- issue phase-A chunks 0..2 ASAP ----
    #pragma unroll
    for (int kn = 0; kn < 3; kn++) {
        unsigned xd = sbase + OFF_XST + kn * XSTAGE_B + (xrow * XST_F + xc4) * 4;
        const float* xsrc = x + (size_t)(tok0 + xrow) * DDIM + kn * KC + xc4;
        #pragma unroll
        for (int p = 0; p < 4; p++)
            cp16(xd + p * 64 * XST_F * 4, xsrc + (size_t)p * 64 * DDIM);
        if (tid < 192) {
            int r = tid >> 2, sg = tid & 3;
            cp16(sbase + OFF_WST + kn * WSTAGE_B + (r * WDST + sg * 8) * 2,
                 g_gw + (size_t)r * DDIM + kn * KC + sg * 8);
        }
        cp_commit();
    }

    // ---- prologue: small precomputed arrays (overlaps flight) ----
    for (int i = tid; i < RDIM; i += THREADS) {
        sumgw_s[i] = g_sumgw[i]; cb_s[i] = g_cb[i]; c48_s[i] = g_c48[i];
    }
    for (int i = tid; i < RDIM * RDIM; i += THREADS) A48T_s[i] = g_A48T[i];

    // ---- phase A mainloop ----
    float acc[6][4];
    #pragma unroll
    for (int j = 0; j < 6; j++)
        #pragma unroll
        for (int q = 0; q < 4; q++) acc[j][q] = 0.f;
    float ps0 = 0.f, pss0 = 0.f, ps1 = 0.f, pss1 = 0.f;

    #pragma unroll 1
    for (int kc = 0; kc < NCHUNK; kc++) {
        int kn = kc + 3;
        if (kn < NCHUNK) {
            int st = kn & 3;
            unsigned xd = sbase + OFF_XST + st * XSTAGE_B + (xrow * XST_F + xc4) * 4;
            const float* xsrc = x + (size_t)(tok0 + xrow) * DDIM + kn * KC + xc4;
            #pragma unroll
            for (int p = 0; p < 4; p++)
                cp16(xd + p * 64 * XST_F * 4, xsrc + (size_t)p * 64 * DDIM);
            if (tid < 192) {
                int r = tid >> 2, sg = tid & 3;
                cp16(sbase + OFF_WST + st * WSTAGE_B + (r * WDST + sg * 8) * 2,
                     g_gw + (size_t)r * DDIM + kn * KC + sg * 8);
            }
        }
        cp_commit();        // possibly empty -> keeps wait<3> template-constant
        cp_wait<3>();
        __syncthreads();

        const float* xs = (const float*)(smem + OFF_XST + (kc & 3) * XSTAGE_B);
        const __nv_bfloat16* wds = (const __nv_bfloat16*)(smem + OFF_WST + (kc & 3) * WSTAGE_B);
        #pragma unroll
        for (int kk = 0; kk < 2; kk++) {
            int cb_ = kk * 16;
            float2 p00 = *(const float2*)(xs + (mrow + g) * XST_F + cb_ + t4 * 2);
            float2 p10 = *(const float2*)(xs + (mrow + g + 8) * XST_F + cb_ + t4 * 2);
            float2 p01 = *(const float2*)(xs + (mrow + g) * XST_F + cb_ + 8 + t4 * 2);
            float2 p11 = *(const float2*)(xs + (mrow + g + 8) * XST_F + cb_ + 8 + t4 * 2);
            ps0  += (p00.x + p00.y) + (p01.x + p01.y);
            pss0 += (p00.x * p00.x + p00.y * p00.y) + (p01.x * p01.x + p01.y * p01.y);
            ps1  += (p10.x + p10.y) + (p11.x + p11.y);
            pss1 += (p10.x * p10.x + p10.y * p10.y) + (p11.x * p11.x + p11.y * p11.y);
            unsigned a0 = pack2(p00.x, p00.y);
            unsigned a1 = pack2(p10.x, p10.y);
            unsigned a2 = pack2(p01.x, p01.y);
            unsigned a3 = pack2(p11.x, p11.y);
            #pragma unroll
            for (int j = 0; j < 6; j++) {
                unsigned b0 = *(const unsigned*)(wds + (j * 8 + g) * WDST + cb_ + t4 * 2);
                unsigned b1 = *(const unsigned*)(wds + (j * 8 + g) * WDST + cb_ + 8 + t4 * 2);
                mma_bf16(acc[j], a0, a1, a2, a3, b0, b1);
            }
        }
    }

    // ---- issue phase-C chunks 0..2 now: overlap stats/y/middle with C lead-in ----
    #pragma unroll
    for (int nn = 0; nn < 3; nn++) {
        unsigned xd = sbase + OFF_XST + nn * XSTAGE_B + (xrow * XST_F + xc4) * 4;
        const float* xsrc = x + (size_t)(tok0 + xrow) * DDIM + nn * KC + xc4;
        #pragma unroll
        for (int p = 0; p < 4; p++)
            cp16(xd + p * 64 * XST_F * 4, xsrc + (size_t)p * 64 * DDIM);
        if (tid < 192) {
            int row = tid / 6, sg = tid % 6;
            cp16(sbase + OFF_WST + nn * WSTAGE_B + (row * WUST + sg * 8) * 2,
                 g_wu + (size_t)(nn * KC + row) * RDIM + sg * 8);
        }
        cp_commit();
    }

    // ---- stats reduce over t4 lanes ----
    #pragma unroll
    for (int off = 1; off <= 2; off <<= 1) {
        ps0  += __shfl_xor_sync(0xffffffffu, ps0, off);
        pss0 += __shfl_xor_sync(0xffffffffu, pss0, off);
        ps1  += __shfl_xor_sync(0xffffffffu, ps1, off);
        pss1 += __shfl_xor_sync(0xffffffffu, pss1, off);
    }
    if (t4 == 0) {
        sum_s[mrow + g] = ps0;     sumsq_s[mrow + g] = pss0;
        sum_s[mrow + g + 8] = ps1; sumsq_s[mrow + g + 8] = pss1;
    }
    __syncthreads();
    if (tid < MTILE) {
        float mu  = sum_s[tid] * (1.0f / DDIM);
        float var = sumsq_s[tid] * (1.0f / DDIM) - mu * mu;
        sum_s[tid]   = mu;
        sumsq_s[tid] = rsqrtf(var + 1e-5f);
    }
    __syncthreads();

    // ---- y = gelu(rinv*(acc - mu*sumgw) + cb) -> bf16 ----
    {
        int r0 = mrow + g, r1 = r0 + 8;
        float mu0 = sum_s[r0], ri0 = sumsq_s[r0];
        float mu1 = sum_s[r1], ri1 = sumsq_s[r1];
        #pragma unroll
        for (int j = 0; j < 6; j++) {
            int c0 = j * 8 + t4 * 2, c1 = c0 + 1;
            float y00 = gelu_exact(ri0 * (acc[j][0] - mu0 * sumgw_s[c0]) + cb_s[c0]);
            float y01 = gelu_exact(ri0 * (acc[j][1] - mu0 * sumgw_s[c1]) + cb_s[c1]);
            float y10 = gelu_exact(ri1 * (acc[j][2] - mu1 * sumgw_s[c0]) + cb_s[c0]);
            float y11 = gelu_exact(ri1 * (acc[j][3] - mu1 * sumgw_s[c1]) + cb_s[c1]);
            *(__nv_bfloat162*)(y_s + r0 * YS_STRIDE + c0) = __floats2bfloat162_rn(y00, y01);
            *(__nv_bfloat162*)(y_s + r1 * YS_STRIDE + c0) = __floats2bfloat162_rn(y10, y11);
        }
    }
    __syncthreads();

    // ---- middle: h2 = gelu(A48 @ y + c48) -> bf16 ----
    {
        int t = tid >> 1;
        int rbase = (tid & 1) * 24;
        const __nv_bfloat16* yrow = y_s + t * YS_STRIDE;
        float h2v[24];
        #pragma unroll
        for (int r = 0; r < 24; r++) h2v[r] = c48_s[rbase + r];
        #pragma unroll 4
        for (int kp2 = 0; kp2 < RDIM / 2; kp2++) {
            __nv_bfloat162 yp = *(const __nv_bfloat162*)(yrow + kp2 * 2);
            float yv0 = __bfloat162float(yp.x), yv1 = __bfloat162float(yp.y);
            const float* a0 = A48T_s + (kp2 * 2) * RDIM + rbase;
            const float* a1 = a0 + RDIM;
            #pragma unroll
            for (int r = 0; r < 24; r++) h2v[r] += yv0 * a0[r] + yv1 * a1[r];
        }
        __nv_bfloat16* op = h2_s + t * H2_STRIDE + rbase;
        #pragma unroll
        for (int r = 0; r < 24; r += 2) {
            __nv_bfloat162 p = __floats2bfloat162_rn(gelu_exact(h2v[r]), gelu_exact(h2v[r + 1]));
            *(__nv_bfloat162*)(op + r) = p;
        }
    }
    __syncthreads();

    // ---- phase C: out = x + scale*(h2 @ wu^T) ----
    float scale = __ldg(scale_p);
    unsigned afr[3][4];
    #pragma unroll
    for (int kk = 0; kk < 3; kk++) {
        afr[kk][0] = *(const unsigned*)(h2_s + (mrow + g) * H2_STRIDE + kk * 16 + t4 * 2);
        afr[kk][1] = *(const unsigned*)(h2_s + (mrow + g + 8) * H2_STRIDE + kk * 16 + t4 * 2);
        afr[kk][2] = *(const unsigned*)(h2_s + (mrow + g) * H2_STRIDE + kk * 16 + 8 + t4 * 2);
        afr[kk][3] = *(const unsigned*)(h2_s + (mrow + g + 8) * H2_STRIDE + kk * 16 + 8 + t4 * 2);
    }

    #pragma unroll 1
    for (int nc = 0; nc < NCHUNK; nc++) {
        int nn = nc + 3;
        if (nn < NCHUNK) {
            int st = nn & 3;
            unsigned xd = sbase + OFF_XST + st * XSTAGE_B + (xrow * XST_F + xc4) * 4;
            const float* xsrc = x + (size_t)(tok0 + xrow) * DDIM + nn * KC + xc4;
            #pragma unroll
            for (int p = 0; p < 4; p++)
                cp16(xd + p * 64 * XST_F * 4, xsrc + (size_t)p * 64 * DDIM);
            if (tid < 192) {
                int row = tid / 6, sg = tid % 6;
                cp16(sbase + OFF_WST + st * WSTAGE_B + (row * WUST + sg * 8) * 2,
                     g_wu + (size_t)(nn * KC + row) * RDIM + sg * 8);
            }
        }
        cp_commit();
        cp_wait<3>();
        __syncthreads();

        const float* xs = (const float*)(smem + OFF_XST + (nc & 3) * XSTAGE_B);
        const __nv_bfloat16* wus = (const __nv_bfloat16*)(smem + OFF_WST + (nc & 3) * WSTAGE_B);

        float uacc[4][4];
        #pragma unroll
        for (int j = 0; j < 4; j++)
            #pragma unroll
            for (int q = 0; q < 4; q++) uacc[j][q] = 0.f;

        #pragma unroll
        for (int kk = 0; kk < 3; kk++) {
            #pragma unroll
            for (int j = 0; j < 4; j++) {
                unsigned b0 = *(const unsigned*)(wus + (j * 8 + g) * WUST + kk * 16 + t4 * 2);
                unsigned b1 = *(const unsigned*)(wus + (j * 8 + g) * WUST + kk * 16 + 8 + t4 * 2);
                mma_bf16(uacc[j], afr[kk][0], afr[kk][1], afr[kk][2], afr[kk][3], b0, b1);
            }
        }
        size_t row0 = (size_t)(tok0 + mrow + g) * DDIM + nc * KC;
        size_t row1 = row0 + 8 * (size_t)DDIM;
        #pragma unroll
        for (int j = 0; j < 4; j++) {
            int lc = j * 8 + t4 * 2;
            float2 xv0 = *(const float2*)(xs + (mrow + g) * XST_F + lc);
            float2 xv1 = *(const float2*)(xs + (mrow + g + 8) * XST_F + lc);
            float2 o0 = make_float2(xv0.x + scale * uacc[j][0], xv0.y + scale * uacc[j][1]);
            float2 o1 = make_float2(xv1.x + scale * uacc[j][2], xv1.y + scale * uacc[j][3]);
            __stcs((float2*)(out + row0 + lc), o0);
            __stcs((float2*)(out + row1 + lc), o1);
        }
    }
}

extern "C" void kernel_launch(void* const* d_in, const int* in_sizes, int n_in,
                              void* d_out, int out_size) {
    const float* x         = (const float*)d_in[0];
    const float* gamma     = (const float*)d_in[1];
    const float* beta      = (const float*)d_in[2];
    const float* w_down    = (const float*)d_in[3];
    const float* w_to_mv   = (const float*)d_in[4];
    const float* w_equi    = (const float*)d_in[5];
    const float* b_equi    = (const float*)d_in[6];
    const float* w_from_mv = (const float*)d_in[7];
    const float* w_up      = (const float*)d_in[8];
    const float* scale     = (const float*)d_in[9];
    float* out = (float*)d_out;

    cudaFuncSetAttribute(fused_kernel, cudaFuncAttributeMaxDynamicSharedMemorySize, SMEM_TOTAL);
    prep_kernel<<<64, 256>>>(gamma, beta, w_down, w_to_mv, w_equi, b_equi, w_from_mv, w_up);
    fused_kernel<<<NCTAS, THREADS, SMEM_TOTAL>>>(x, scale, out);
}

// round 10
// speedup vs baseline: 1.7264x; 1.0412x over previous
#include <cuda_runtime.h>
#include <cuda_bf16.h>

#define TOKENS 32768
#define DDIM 1024
#define RDIM 48
#define MTILE 256
#define THREADS 512
#define NCTAS (TOKENS / MTILE)   // 128 CTAs -> one wave
#define KC 32
#define NCHUNK (DDIM / KC)       // 32
#define NSTAGE 4

#define XST_F 36                 // fp32 elems; 144B rows
#define WDST 40                  // bf16 elems; 80B rows  (8-row LDSM conflict-free)
#define WUST 56                  // bf16 elems; 112B rows (8-row LDSM conflict-free)
#define YS_STRIDE 52             // bf16
#define H2_STRIDE 56             // bf16

#define XSTAGE_B (MTILE * XST_F * 4)     // 36864
#define WSTAGE_B (RDIM * WDST * 2)       // 3840 (>= wu stage 3584)

// ---- smem layout (bytes) ----
#define OFF_XST 0                                   // 4 x-stages: 147456
#define OFF_WST (OFF_XST + NSTAGE * XSTAGE_B)       // 4 w-stages: 15360
#define OFF_H2  (OFF_WST + NSTAGE * WSTAGE_B)       // 28672
#define OFF_Y   (OFF_H2 + MTILE * H2_STRIDE * 2)    // 26624
#define OFF_SUM (OFF_Y + MTILE * YS_STRIDE * 2)
#define OFF_SSQ (OFF_SUM + MTILE * 4)
#define OFF_SGW (OFF_SSQ + MTILE * 4)
#define OFF_CB  (OFF_SGW + RDIM * 4)
#define OFF_C48 (OFF_CB + RDIM * 4)
#define OFF_A48 (OFF_C48 + RDIM * 4)
#define SMEM_TOTAL (OFF_A48 + RDIM * RDIM * 4)      // 229952 <= 232448

// ---- global scratch (prep output) ----
__device__ __align__(16) __nv_bfloat16 g_gw[RDIM * DDIM];   // gamma (*) w_down
__device__ __align__(16) __nv_bfloat16 g_wu[DDIM * RDIM];
__device__ float g_sumgw[RDIM];
__device__ float g_cb[RDIM];
__device__ float g_c48[RDIM];
__device__ float g_A48T[RDIM * RDIM];

__device__ __forceinline__ float gelu_exact(float v) {
    return 0.5f * v * (1.0f + erff(v * 0.70710678118654752440f));
}

__device__ __forceinline__ void mma_bf16(float* c, unsigned a0, unsigned a1, unsigned a2,
                                         unsigned a3, unsigned b0, unsigned b1) {
    asm volatile(
        "mma.sync.aligned.m16n8k16.row.col.f32.bf16.bf16.f32 "
        "{%0,%1,%2,%3}, {%4,%5,%6,%7}, {%8,%9}, {%0,%1,%2,%3};\n"
        : "+f"(c[0]), "+f"(c[1]), "+f"(c[2]), "+f"(c[3])
        : "r"(a0), "r"(a1), "r"(a2), "r"(a3), "r"(b0), "r"(b1));
}

__device__ __forceinline__ void ldsm_x4(unsigned* r, unsigned addr) {
    asm volatile("ldmatrix.sync.aligned.m8n8.x4.shared.b16 {%0,%1,%2,%3}, [%4];"
                 : "=r"(r[0]), "=r"(r[1]), "=r"(r[2]), "=r"(r[3]) : "r"(addr));
}

__device__ __forceinline__ unsigned pack2(float a, float b) {
    __nv_bfloat162 p = __floats2bfloat162_rn(a, b);
    return *(unsigned*)&p;
}
__device__ __forceinline__ uint2 pack_bf16x4(float a, float b, float c, float d) {
    uint2 pk;
    pk.x = pack2(a, b);
    pk.y = pack2(c, d);
    return pk;
}

__device__ __forceinline__ void cp16(unsigned dst, const void* src) {
    asm volatile("cp.async.cg.shared.global [%0], [%1], 16;\n" :: "r"(dst), "l"(src));
}
__device__ __forceinline__ void cp_commit() {
    asm volatile("cp.async.commit_group;\n");
}
template <int N>
__device__ __forceinline__ void cp_wait() {
    asm volatile("cp.async.wait_group %0;\n" :: "n"(N));
}

// ============================================================================
// prep v2: vectorized, fully parallel. grid 128 x 256.
// ============================================================================
__global__ void prep_kernel(const float* __restrict__ gamma, const float* __restrict__ beta,
                            const float* __restrict__ w_down, const float* __restrict__ w_to_mv,
                            const float* __restrict__ w_equi, const float* __restrict__ b_equi,
                            const float* __restrict__ w_from_mv, const float* __restrict__ w_up) {
    int tid = threadIdx.x, lane = tid & 31;
    int gtid = blockIdx.x * blockDim.x + tid;
    int nth = gridDim.x * blockDim.x;
    int gwarp = gtid >> 5;

    if (gwarp < RDIM) {   // one warp per row: gw (bf16) + sumgw + cb in one pass
        int r = gwarp;
        float s = 0.f, cb = 0.f;
        #pragma unroll
        for (int it = 0; it < 8; it++) {
            int d = it * 128 + lane * 4;
            float4 w  = *(const float4*)(w_down + (size_t)r * DDIM + d);
            float4 gv = *(const float4*)(gamma + d);
            float4 bv = *(const float4*)(beta + d);
            uint2 pk = pack_bf16x4(w.x * gv.x, w.y * gv.y, w.z * gv.z, w.w * gv.w);
            *(uint2*)(g_gw + (size_t)r * DDIM + d) = pk;
            __nv_bfloat162 b0 = *(__nv_bfloat162*)&pk.x;
            __nv_bfloat162 b1 = *(__nv_bfloat162*)&pk.y;
            s += __bfloat162float(b0.x) + __bfloat162float(b0.y)
               + __bfloat162float(b1.x) + __bfloat162float(b1.y);
            cb += w.x * bv.x + w.y * bv.y + w.z * bv.z + w.w * bv.w;
        }
        #pragma unroll
        for (int off = 16; off; off >>= 1) {
            s  += __shfl_xor_sync(0xffffffffu, s, off);
            cb += __shfl_xor_sync(0xffffffffu, cb, off);
        }
        if (lane == 0) { g_sumgw[r] = s; g_cb[r] = cb; }
    }
    for (int i = gtid; i < DDIM * RDIM / 4; i += nth) {
        float4 v = ((const float4*)w_up)[i];
        ((uint2*)g_wu)[i] = pack_bf16x4(v.x, v.y, v.z, v.w);
    }
    for (int i = gtid; i < RDIM * RDIM; i += nth) {
        int rp = i / RDIM, r = i - rp * RDIM;
        float a = 0.f;
        #pragma unroll
        for (int m = 0; m < 16; m++) {
            int gidx = (m == 0) ? 0 : (m < 5) ? 1 : (m < 11) ? 2 : (m < 15) ? 3 : 4;
            a += __ldg(w_from_mv + r * 16 + m) * __ldg(w_equi + gidx)
               * __ldg(w_to_mv + m * RDIM + rp);
        }
        g_A48T[i] = a;
    }
    for (int i = gtid; i < RDIM; i += nth)
        g_c48[i] = __ldg(w_from_mv + i * 16) * __ldg(b_equi);
}

// ============================================================================
__global__ void __launch_bounds__(THREADS, 1) fused_kernel(
    const float* __restrict__ x, const float* __restrict__ scale_p,
    float* __restrict__ out)
{
    extern __shared__ char smem[];
    const unsigned sbase = (unsigned)__cvta_generic_to_shared(smem);
    __nv_bfloat16* h2_s = (__nv_bfloat16*)(smem + OFF_H2);
    __nv_bfloat16* y_s  = (__nv_bfloat16*)(smem + OFF_Y);
    float* sum_s   = (float*)(smem + OFF_SUM);
    float* sumsq_s = (float*)(smem + OFF_SSQ);
    float* sumgw_s = (float*)(smem + OFF_SGW);
    float* cb_s    = (float*)(smem + OFF_CB);
    float* c48_s   = (float*)(smem + OFF_C48);
    float* A48T_s  = (float*)(smem + OFF_A48);

    const int tid = threadIdx.x, lane = tid & 31, warp = tid >> 5;
    const int g = lane >> 2, t4 = lane & 3;
    const int tok0 = blockIdx.x * MTILE;
    const int mrow = warp * 16;

    // LDSM lane mapping: row-within-pairblock + k-half
    const int bn = ((lane >> 4) << 3) + (lane & 7);
    const int kh = (lane >> 3) & 1;

    const int xrow = tid >> 3, xc4 = (tid & 7) * 4;   // x cp mapping: 4 ops/thread

    // ---- issue phase-A chunks 0..2 ASAP ----
    #pragma unroll
    for (int kn = 0; kn < 3; kn++) {
        unsigned xd = sbase + OFF_XST + kn * XSTAGE_B + (xrow * XST_F + xc4) * 4;
        const float* xsrc = x + (size_t)(tok0 + xrow) * DDIM + kn * KC + xc4;
        #pragma unroll
        for (int p = 0; p < 4; p++)
            cp16(xd + p * 64 * XST_F * 4, xsrc + (size_t)p * 64 * DDIM);
        if (tid < 192) {
            int r = tid >> 2, sg = tid & 3;
            cp16(sbase + OFF_WST + kn * WSTAGE_B + (r * WDST + sg * 8) * 2,
                 g_gw + (size_t)r * DDIM + kn * KC + sg * 8);
        }
        cp_commit();
    }

    // ---- prologue: small precomputed arrays (overlaps flight) ----
    for (int i = tid; i < RDIM; i += THREADS) {
        sumgw_s[i] = g_sumgw[i]; cb_s[i] = g_cb[i]; c48_s[i] = g_c48[i];
    }
    for (int i = tid; i < RDIM * RDIM; i += THREADS) A48T_s[i] = g_A48T[i];

    // ---- phase A mainloop ----
    float acc[6][4];
    #pragma unroll
    for (int j = 0; j < 6; j++)
        #pragma unroll
        for (int q = 0; q < 4; q++) acc[j][q] = 0.f;
    float ps0 = 0.f, pss0 = 0.f, ps1 = 0.f, pss1 = 0.f;

    #pragma unroll 1
    for (int kc = 0; kc < NCHUNK; kc++) {
        int kn = kc + 3;
        if (kn < NCHUNK) {
            int st = kn & 3;
            unsigned xd = sbase + OFF_XST + st * XSTAGE_B + (xrow * XST_F + xc4) * 4;
            const float* xsrc = x + (size_t)(tok0 + xrow) * DDIM + kn * KC + xc4;
            #pragma unroll
            for (int p = 0; p < 4; p++)
                cp16(xd + p * 64 * XST_F * 4, xsrc + (size_t)p * 64 * DDIM);
            if (tid < 192) {
                int r = tid >> 2, sg = tid & 3;
                cp16(sbase + OFF_WST + st * WSTAGE_B + (r * WDST + sg * 8) * 2,
                     g_gw + (size_t)r * DDIM + kn * KC + sg * 8);
            }
        }
        cp_commit();        // possibly empty -> keeps wait<3> template-constant
        cp_wait<3>();
        __syncthreads();

        const float* xs = (const float*)(smem + OFF_XST + (kc & 3) * XSTAGE_B);
        const unsigned wb = sbase + OFF_WST + (kc & 3) * WSTAGE_B + (bn * WDST + kh * 8) * 2;
        #pragma unroll
        for (int kk = 0; kk < 2; kk++) {
            int cb_ = kk * 16;
            float2 p00 = *(const float2*)(xs + (mrow + g) * XST_F + cb_ + t4 * 2);
            float2 p10 = *(const float2*)(xs + (mrow + g + 8) * XST_F + cb_ + t4 * 2);
            float2 p01 = *(const float2*)(xs + (mrow + g) * XST_F + cb_ + 8 + t4 * 2);
            float2 p11 = *(const float2*)(xs + (mrow + g + 8) * XST_F + cb_ + 8 + t4 * 2);
            ps0  += (p00.x + p00.y) + (p01.x + p01.y);
            pss0 += (p00.x * p00.x + p00.y * p00.y) + (p01.x * p01.x + p01.y * p01.y);
            ps1  += (p10.x + p10.y) + (p11.x + p11.y);
            pss1 += (p10.x * p10.x + p10.y * p10.y) + (p11.x * p11.x + p11.y * p11.y);
            unsigned a0 = pack2(p00.x, p00.y);
            unsigned a1 = pack2(p10.x, p10.y);
            unsigned a2 = pack2(p01.x, p01.y);
            unsigned a3 = pack2(p11.x, p11.y);
            unsigned br[3][4];
            #pragma unroll
            for (int p = 0; p < 3; p++)
                ldsm_x4(br[p], wb + p * 16 * WDST * 2 + cb_ * 2);
            #pragma unroll
            for (int j = 0; j < 6; j++)
                mma_bf16(acc[j], a0, a1, a2, a3, br[j >> 1][(j & 1) * 2], br[j >> 1][(j & 1) * 2 + 1]);
        }
    }

    // ---- issue phase-C chunks 0..2 now: overlap stats/y/middle with C lead-in ----
    #pragma unroll
    for (int nn = 0; nn < 3; nn++) {
        unsigned xd = sbase + OFF_XST + nn * XSTAGE_B + (xrow * XST_F + xc4) * 4;
        const float* xsrc = x + (size_t)(tok0 + xrow) * DDIM + nn * KC + xc4;
        #pragma unroll
        for (int p = 0; p < 4; p++)
            cp16(xd + p * 64 * XST_F * 4, xsrc + (size_t)p * 64 * DDIM);
        if (tid < 192) {
            int row = tid / 6, sg = tid % 6;
            cp16(sbase + OFF_WST + nn * WSTAGE_B + (row * WUST + sg * 8) * 2,
                 g_wu + (size_t)(nn * KC + row) * RDIM + sg * 8);
        }
        cp_commit();
    }

    // ---- stats reduce over t4 lanes ----
    #pragma unroll
    for (int off = 1; off <= 2; off <<= 1) {
        ps0  += __shfl_xor_sync(0xffffffffu, ps0, off);
        pss0 += __shfl_xor_sync(0xffffffffu, pss0, off);
        ps1  += __shfl_xor_sync(0xffffffffu, ps1, off);
        pss1 += __shfl_xor_sync(0xffffffffu, pss1, off);
    }
    if (t4 == 0) {
        sum_s[mrow + g] = ps0;     sumsq_s[mrow + g] = pss0;
        sum_s[mrow + g + 8] = ps1; sumsq_s[mrow + g + 8] = pss1;
    }
    __syncthreads();
    if (tid < MTILE) {
        float mu  = sum_s[tid] * (1.0f / DDIM);
        float var = sumsq_s[tid] * (1.0f / DDIM) - mu * mu;
        sum_s[tid]   = mu;
        sumsq_s[tid] = rsqrtf(var + 1e-5f);
    }
    __syncthreads();

    // ---- y = gelu(rinv*(acc - mu*sumgw) + cb) -> bf16 ----
    {
        int r0 = mrow + g, r1 = r0 + 8;
        float mu0 = sum_s[r0], ri0 = sumsq_s[r0];
        float mu1 = sum_s[r1], ri1 = sumsq_s[r1];
        #pragma unroll
        for (int j = 0; j < 6; j++) {
            int c0 = j * 8 + t4 * 2, c1 = c0 + 1;
            float y00 = gelu_exact(ri0 * (acc[j][0] - mu0 * sumgw_s[c0]) + cb_s[c0]);
            float y01 = gelu_exact(ri0 * (acc[j][1] - mu0 * sumgw_s[c1]) + cb_s[c1]);
            float y10 = gelu_exact(ri1 * (acc[j][2] - mu1 * sumgw_s[c0]) + cb_s[c0]);
            float y11 = gelu_exact(ri1 * (acc[j][3] - mu1 * sumgw_s[c1]) + cb_s[c1]);
            *(__nv_bfloat162*)(y_s + r0 * YS_STRIDE + c0) = __floats2bfloat162_rn(y00, y01);
            *(__nv_bfloat162*)(y_s + r1 * YS_STRIDE + c0) = __floats2bfloat162_rn(y10, y11);
        }
    }
    __syncthreads();

    // ---- middle: h2 = gelu(A48 @ y + c48) -> bf16 ----
    {
        int t = tid >> 1;
        int rbase = (tid & 1) * 24;
        const __nv_bfloat16* yrow = y_s + t * YS_STRIDE;
        float h2v[24];
        #pragma unroll
        for (int r = 0; r < 24; r++) h2v[r] = c48_s[rbase + r];
        #pragma unroll 4
        for (int kp2 = 0; kp2 < RDIM / 2; kp2++) {
            __nv_bfloat162 yp = *(const __nv_bfloat162*)(yrow + kp2 * 2);
            float yv0 = __bfloat162float(yp.x), yv1 = __bfloat162float(yp.y);
            const float* a0 = A48T_s + (kp2 * 2) * RDIM + rbase;
            const float* a1 = a0 + RDIM;
            #pragma unroll
            for (int r = 0; r < 24; r++) h2v[r] += yv0 * a0[r] + yv1 * a1[r];
        }
        __nv_bfloat16* op = h2_s + t * H2_STRIDE + rbase;
        #pragma unroll
        for (int r = 0; r < 24; r += 2) {
            __nv_bfloat162 p = __floats2bfloat162_rn(gelu_exact(h2v[r]), gelu_exact(h2v[r + 1]));
            *(__nv_bfloat162*)(op + r) = p;
        }
    }
    __syncthreads();

    // ---- phase C: out = x + scale*(h2 @ wu^T) ----
    float scale = __ldg(scale_p);
    unsigned afr[3][4];
    #pragma unroll
    for (int kk = 0; kk < 3; kk++) {
        afr[kk][0] = *(const unsigned*)(h2_s + (mrow + g) * H2_STRIDE + kk * 16 + t4 * 2);
        afr[kk][1] = *(const unsigned*)(h2_s + (mrow + g + 8) * H2_STRIDE + kk * 16 + t4 * 2);
        afr[kk][2] = *(const unsigned*)(h2_s + (mrow + g) * H2_STRIDE + kk * 16 + 8 + t4 * 2);
        afr[kk][3] = *(const unsigned*)(h2_s + (mrow + g + 8) * H2_STRIDE + kk * 16 + 8 + t4 * 2);
    }

    #pragma unroll 1
    for (int nc = 0; nc < NCHUNK; nc++) {
        int nn = nc + 3;
        if (nn < NCHUNK) {
            int st = nn & 3;
            unsigned xd = sbase + OFF_XST + st * XSTAGE_B + (xrow * XST_F + xc4) * 4;
            const float* xsrc = x + (size_t)(tok0 + xrow) * DDIM + nn * KC + xc4;
            #pragma unroll
            for (int p = 0; p < 4; p++)
                cp16(xd + p * 64 * XST_F * 4, xsrc + (size_t)p * 64 * DDIM);
            if (tid < 192) {
                int row = tid / 6, sg = tid % 6;
                cp16(sbase + OFF_WST + st * WSTAGE_B + (row * WUST + sg * 8) * 2,
                     g_wu + (size_t)(nn * KC + row) * RDIM + sg * 8);
            }
        }
        cp_commit();
        cp_wait<3>();
        __syncthreads();

        const float* xs = (const float*)(smem + OFF_XST + (nc & 3) * XSTAGE_B);
        const unsigned wub = sbase + OFF_WST + (nc & 3) * WSTAGE_B + (bn * WUST + kh * 8) * 2;

        float uacc[4][4];
        #pragma unroll
        for (int j = 0; j < 4; j++)
            #pragma unroll
            for (int q = 0; q < 4; q++) uacc[j][q] = 0.f;

        #pragma unroll
        for (int kk = 0; kk < 3; kk++) {
            unsigned br[2][4];
            #pragma unroll
            for (int p = 0; p < 2; p++)
                ldsm_x4(br[p], wub + p * 16 * WUST * 2 + kk * 32);
            #pragma unroll
            for (int j = 0; j < 4; j++)
                mma_bf16(uacc[j], afr[kk][0], afr[kk][1], afr[kk][2], afr[kk][3],
                         br[j >> 1][(j & 1) * 2], br[j >> 1][(j & 1) * 2 + 1]);
        }
        size_t row0 = (size_t)(tok0 + mrow + g) * DDIM + nc * KC;
        size_t row1 = row0 + 8 * (size_t)DDIM;
        #pragma unroll
        for (int j = 0; j < 4; j++) {
            int lc = j * 8 + t4 * 2;
            float2 xv0 = *(const float2*)(xs + (mrow + g) * XST_F + lc);
            float2 xv1 = *(const float2*)(xs + (mrow + g + 8) * XST_F + lc);
            float2 o0 = make_float2(xv0.x + scale * uacc[j][0], xv0.y + scale * uacc[j][1]);
            float2 o1 = make_float2(xv1.x + scale * uacc[j][2], xv1.y + scale * uacc[j][3]);
            __stcs((float2*)(out + row0 + lc), o0);
            __stcs((float2*)(out + row1 + lc), o1);
        }
    }
}

extern "C" void kernel_launch(void* const* d_in, const int* in_sizes, int n_in,
                              void* d_out, int out_size) {
    const float* x         = (const float*)d_in[0];
    const float* gamma     = (const float*)d_in[1];
    const float* beta      = (const float*)d_in[2];
    const float* w_down    = (const float*)d_in[3];
    const float* w_to_mv   = (const float*)d_in[4];
    const float* w_equi    = (const float*)d_in[5];
    const float* b_equi    = (const float*)d_in[6];
    const float* w_from_mv = (const float*)d_in[7];
    const float* w_up      = (const float*)d_in[8];
    const float* scale     = (const float*)d_in[9];
    float* out = (float*)d_out;

    cudaFuncSetAttribute(fused_kernel, cudaFuncAttributeMaxDynamicSharedMemorySize, SMEM_TOTAL);
    prep_kernel<<<128, 256>>>(gamma, beta, w_down, w_to_mv, w_equi, b_equi, w_from_mv, w_up);
    fused_kernel<<<NCTAS, THREADS, SMEM_TOTAL>>>(x, scale, out);
}